// round 2
// baseline (speedup 1.0000x reference)
#include <cuda_runtime.h>
#include <cstdint>

#define HEADS 6
#define NTOK  64
#define DIM   96
#define HD    16
#define NW    512

// Precomputed relative-position bias, (H, N, N) layout.
__device__ float g_bias[HEADS * NTOK * NTOK];

__global__ void bias_prep_kernel(const float* __restrict__ rpb,
                                 const int* __restrict__ ridx) {
    int i = blockIdx.x * blockDim.x + threadIdx.x;   // 0 .. 6*64*64-1
    if (i < HEADS * NTOK * NTOK) {
        int h  = i / (NTOK * NTOK);
        int nm = i % (NTOK * NTOK);
        g_bias[i] = rpb[ridx[nm] * HEADS + h];
    }
}

// One CTA per window. 256 threads = (ty 0..15) x (tx 0..15).
// SMEM layout (floats):
//   xs [0,      6144)  : x tile 64x96, later reused as attention output o
//   wa [6144,   9216)  : weight chunk 32x96 (GEMM stages) / attn 32x64 (attn stage)
//   qs [9216,  15360)  : Q 64x96 (pre-scaled)
//   ks [15360, 21568)  : K 64x97 (padded -> conflict-free K^T reads)
//   vs [21568, 27712)  : V 64x96
#define SMEM_FLOATS 27712

__global__ __launch_bounds__(256, 2)
void win_attn_kernel(const float* __restrict__ x,
                     const float* __restrict__ mask,
                     const float* __restrict__ qkv_w,
                     const float* __restrict__ qkv_b,
                     const float* __restrict__ proj_w,
                     const float* __restrict__ proj_b,
                     float* __restrict__ out,
                     int n_windows)
{
    extern __shared__ float sm[];
    float* xs = sm;
    float* wa = sm + 6144;
    float* qs = sm + 9216;
    float* ks = sm + 15360;
    float* vs = sm + 21568;

    const int tid = threadIdx.x;
    const int tx  = tid & 15;
    const int ty  = tid >> 4;
    const int b   = blockIdx.x;
    if (b >= n_windows) return;

    // ---- load x tile (64x96 floats = 1536 float4) ----
    {
        const float4* xg = reinterpret_cast<const float4*>(x + (size_t)b * NTOK * DIM);
        float4* xl = reinterpret_cast<float4*>(xs);
        #pragma unroll
        for (int u = 0; u < 6; ++u) xl[tid + u * 256] = xg[tid + u * 256];
    }
    __syncthreads();

    // =========================== QKV GEMM ===========================
    // C[64][96] per pass p: rows r_i = ty + i*16, cols c_j = tx + j*16.
    #pragma unroll 1
    for (int p = 0; p < 3; ++p) {
        float acc[4][6];
        #pragma unroll
        for (int j = 0; j < 6; ++j) {
            float bj = qkv_b[p * 96 + tx + j * 16];
            #pragma unroll
            for (int i = 0; i < 4; ++i) acc[i][j] = bj;
        }

        #pragma unroll 1
        for (int kb = 0; kb < 96; kb += 32) {
            __syncthreads();   // previous chunk fully consumed
            // stage 32x96 weight chunk into SMEM (768 float4)
            {
                const float* wsrc = qkv_w + (size_t)kb * 288 + p * 96;
                #pragma unroll
                for (int u = 0; u < 3; ++u) {
                    int e = tid + u * 256;
                    int r = e / 24, c = e % 24;
                    reinterpret_cast<float4*>(wa)[e] =
                        *reinterpret_cast<const float4*>(wsrc + r * 288 + c * 4);
                }
            }
            __syncthreads();

            #pragma unroll
            for (int k4 = 0; k4 < 8; ++k4) {
                float4 xr[4];
                #pragma unroll
                for (int i = 0; i < 4; ++i)
                    xr[i] = *reinterpret_cast<const float4*>(
                        &xs[(ty + i * 16) * 96 + kb + k4 * 4]);
                #pragma unroll
                for (int t = 0; t < 4; ++t) {
                    float wv[6];
                    #pragma unroll
                    for (int j = 0; j < 6; ++j)
                        wv[j] = wa[(k4 * 4 + t) * 96 + tx + j * 16];
                    #pragma unroll
                    for (int i = 0; i < 4; ++i) {
                        float xv = (t == 0) ? xr[i].x : (t == 1) ? xr[i].y
                                 : (t == 2) ? xr[i].z : xr[i].w;
                        #pragma unroll
                        for (int j = 0; j < 6; ++j)
                            acc[i][j] = fmaf(xv, wv[j], acc[i][j]);
                    }
                }
            }
        }

        float* dst      = (p == 0) ? qs : (p == 1) ? ks : vs;
        const int strd  = (p == 1) ? 97 : 96;
        const float scl = (p == 0) ? 0.25f : 1.0f;   // hd^-0.5 = 16^-0.5
        #pragma unroll
        for (int i = 0; i < 4; ++i)
            #pragma unroll
            for (int j = 0; j < 6; ++j)
                dst[(ty + i * 16) * strd + tx + j * 16] = acc[i][j] * scl;
    }
    __syncthreads();

    // =========================== attention ===========================
    const float* mp = mask + (size_t)(b % NW) * NTOK * NTOK;

    #pragma unroll 1
    for (int h = 0; h < HEADS; ++h) {
        const int cb = h * HD;
        #pragma unroll 1
        for (int nh = 0; nh < 2; ++nh) {
            const int n0 = nh * 32;

            // ---- QK^T: thread -> rows n0+ty*2+{0,1}, cols tx+{0..3}*16 ----
            float a2[2][4] = {{0.f,0.f,0.f,0.f},{0.f,0.f,0.f,0.f}};
            #pragma unroll
            for (int d = 0; d < 16; ++d) {
                float qv[2], kv[4];
                #pragma unroll
                for (int i = 0; i < 2; ++i)
                    qv[i] = qs[(n0 + ty * 2 + i) * 96 + cb + d];
                #pragma unroll
                for (int j = 0; j < 4; ++j)
                    kv[j] = ks[(tx + j * 16) * 97 + cb + d];
                #pragma unroll
                for (int i = 0; i < 2; ++i)
                    #pragma unroll
                    for (int j = 0; j < 4; ++j)
                        a2[i][j] = fmaf(qv[i], kv[j], a2[i][j]);
            }
            #pragma unroll
            for (int i = 0; i < 2; ++i) {
                int n = n0 + ty * 2 + i;
                #pragma unroll
                for (int j = 0; j < 4; ++j) {
                    int m = tx + j * 16;
                    wa[(n - n0) * 64 + m] =
                        a2[i][j] + g_bias[h * 4096 + n * 64 + m] + mp[n * 64 + m];
                }
            }
            __syncthreads();

            // ---- softmax: 32 rows, 8 threads/row, 8 cols/thread ----
            {
                int r  = tid >> 3;
                int c0 = (tid & 7) * 8;
                float* row = wa + r * 64 + c0;
                float4 va = reinterpret_cast<float4*>(row)[0];
                float4 vb = reinterpret_cast<float4*>(row)[1];
                float mx = fmaxf(fmaxf(fmaxf(va.x, va.y), fmaxf(va.z, va.w)),
                                 fmaxf(fmaxf(vb.x, vb.y), fmaxf(vb.z, vb.w)));
                #pragma unroll
                for (int o = 4; o > 0; o >>= 1)
                    mx = fmaxf(mx, __shfl_xor_sync(0xffffffffu, mx, o, 8));
                va.x = __expf(va.x - mx); va.y = __expf(va.y - mx);
                va.z = __expf(va.z - mx); va.w = __expf(va.w - mx);
                vb.x = __expf(vb.x - mx); vb.y = __expf(vb.y - mx);
                vb.z = __expf(vb.z - mx); vb.w = __expf(vb.w - mx);
                float s = va.x + va.y + va.z + va.w + vb.x + vb.y + vb.z + vb.w;
                #pragma unroll
                for (int o = 4; o > 0; o >>= 1)
                    s += __shfl_xor_sync(0xffffffffu, s, o, 8);
                float inv = 1.0f / s;
                va.x *= inv; va.y *= inv; va.z *= inv; va.w *= inv;
                vb.x *= inv; vb.y *= inv; vb.z *= inv; vb.w *= inv;
                reinterpret_cast<float4*>(row)[0] = va;
                reinterpret_cast<float4*>(row)[1] = vb;
            }
            __syncthreads();

            // ---- PV: thread -> rows n0+ty*2+{0,1}, col d = tx ----
            {
                float oa0 = 0.f, oa1 = 0.f;
                #pragma unroll 4
                for (int m = 0; m < 64; ++m) {
                    float vv = vs[m * 96 + cb + tx];
                    oa0 = fmaf(wa[(ty * 2 + 0) * 64 + m], vv, oa0);
                    oa1 = fmaf(wa[(ty * 2 + 1) * 64 + m], vv, oa1);
                }
                xs[(n0 + ty * 2 + 0) * 96 + cb + tx] = oa0;   // o reuses xs
                xs[(n0 + ty * 2 + 1) * 96 + cb + tx] = oa1;
            }
            __syncthreads();
        }
    }

    // =========================== proj GEMM ===========================
    {
        float acc[4][6];
        #pragma unroll
        for (int j = 0; j < 6; ++j) {
            float bj = proj_b[tx + j * 16];
            #pragma unroll
            for (int i = 0; i < 4; ++i) acc[i][j] = bj;
        }

        #pragma unroll 1
        for (int kb = 0; kb < 96; kb += 32) {
            __syncthreads();
            #pragma unroll
            for (int u = 0; u < 3; ++u) {
                int e = tid + u * 256;
                int r = e / 24, c = e % 24;
                reinterpret_cast<float4*>(wa)[e] =
                    *reinterpret_cast<const float4*>(proj_w + (size_t)(kb + r) * 96 + c * 4);
            }
            __syncthreads();

            #pragma unroll
            for (int k4 = 0; k4 < 8; ++k4) {
                float4 xr[4];
                #pragma unroll
                for (int i = 0; i < 4; ++i)
                    xr[i] = *reinterpret_cast<const float4*>(
                        &xs[(ty + i * 16) * 96 + kb + k4 * 4]);
                #pragma unroll
                for (int t = 0; t < 4; ++t) {
                    float wv[6];
                    #pragma unroll
                    for (int j = 0; j < 6; ++j)
                        wv[j] = wa[(k4 * 4 + t) * 96 + tx + j * 16];
                    #pragma unroll
                    for (int i = 0; i < 4; ++i) {
                        float xv = (t == 0) ? xr[i].x : (t == 1) ? xr[i].y
                                 : (t == 2) ? xr[i].z : xr[i].w;
                        #pragma unroll
                        for (int j = 0; j < 6; ++j)
                            acc[i][j] = fmaf(xv, wv[j], acc[i][j]);
                    }
                }
            }
        }

        float* og = out + (size_t)b * NTOK * DIM;
        #pragma unroll
        for (int i = 0; i < 4; ++i)
            #pragma unroll
            for (int j = 0; j < 6; ++j)
                og[(ty + i * 16) * 96 + tx + j * 16] = acc[i][j];
    }
}

extern "C" void kernel_launch(void* const* d_in, const int* in_sizes, int n_in,
                              void* d_out, int out_size)
{
    const float* x      = (const float*)d_in[0];
    const float* mask   = (const float*)d_in[1];
    const float* qkv_w  = (const float*)d_in[2];
    const float* qkv_b  = (const float*)d_in[3];
    const float* proj_w = (const float*)d_in[4];
    const float* proj_b = (const float*)d_in[5];
    const float* rpb    = (const float*)d_in[6];
    const int*   ridx   = (const int*)d_in[7];
    float* out = (float*)d_out;

    const int n_windows = in_sizes[0] / (NTOK * DIM);   // 8192

    static bool attr_set = false;
    // cudaFuncSetAttribute is not a stream operation; safe during capture.
    cudaFuncSetAttribute(win_attn_kernel,
                         cudaFuncAttributeMaxDynamicSharedMemorySize,
                         SMEM_FLOATS * sizeof(float));
    (void)attr_set;

    // 1) gather relative-position bias into (H,N,N) device-global table
    bias_prep_kernel<<<96, 256>>>(rpb, ridx);
    // 2) fused window attention, one CTA per window
    win_attn_kernel<<<n_windows, 256, SMEM_FLOATS * sizeof(float)>>>(
        x, mask, qkv_w, qkv_b, proj_w, proj_b, out, n_windows);
}

// round 3
// speedup vs baseline: 1.1967x; 1.1967x over previous
#include <cuda_runtime.h>
#include <cstdint>

#define HEADS 6
#define NTOK  64
#define DIM   96
#define NW    512

typedef unsigned long long ull;

// ---------------- packed f32x2 helpers (sm_103a FFMA2 path) ----------------
__device__ __forceinline__ ull pk(float lo, float hi) {
    ull r; asm("mov.b64 %0, {%1,%2};" : "=l"(r) : "f"(lo), "f"(hi)); return r;
}
__device__ __forceinline__ void upk(ull v, float& lo, float& hi) {
    asm("mov.b64 {%0,%1}, %2;" : "=f"(lo), "=f"(hi) : "l"(v));
}
__device__ __forceinline__ ull f2fma(ull a, ull b, ull c) {
    ull d; asm("fma.rn.f32x2 %0, %1, %2, %3;" : "=l"(d) : "l"(a), "l"(b), "l"(c)); return d;
}
__device__ __forceinline__ ull f2mul(ull a, ull b) {
    ull d; asm("mul.rn.f32x2 %0, %1, %2;" : "=l"(d) : "l"(a), "l"(b)); return d;
}

// Combined (rpb-gather + shift-mask) table: [w][h][n][m] fp32, ~50MB.
__device__ float cmb[NW * HEADS * NTOK * NTOK];

__global__ void prep_kernel(const float* __restrict__ rpb,
                            const int* __restrict__ ridx,
                            const float* __restrict__ mask) {
    int i = blockIdx.x * 256 + threadIdx.x;
    if (i >= NW * HEADS * NTOK * NTOK) return;
    int w   = i / (HEADS * 4096);
    int rem = i % (HEADS * 4096);
    int h   = rem / 4096;
    int nm  = rem % 4096;
    cmb[i] = rpb[ridx[nm] * HEADS + h] + mask[w * 4096 + nm];
}

// SMEM layout (floats). All matrices stored transposed: [channel][token].
//   XST [0,     6336) : x^T [96][s66]; dead after QKV -> aliased by ATTN [64][s68]
//   WST [6336,  7872) : weight staging chunk [k=16][96]
//   QT  [7872, 14208) : Q^T [96][s66] (pre-scaled); per-head overwritten by o^T
//   KT  [14208,20736) : K^T [96][s68] (16B-aligned rows for float4 reads)
//   VT  [20736,27072) : V^T [96][s66] (conflict-free PV LDS.64)
#define XST 0
#define ATTN 0
#define WST 6336
#define QT  7872
#define KT  14208
#define VT  20736
#define SMEM_FLOATS 27072

__global__ __launch_bounds__(256, 2)
void win_attn_kernel(const float* __restrict__ x,
                     const float* __restrict__ qkv_w,
                     const float* __restrict__ qkv_b,
                     const float* __restrict__ proj_w,
                     const float* __restrict__ proj_b,
                     float* __restrict__ out)
{
    extern __shared__ float sm[];
    const int tid = threadIdx.x;
    const int b   = blockIdx.x;

    // ---- load x (64x96) and transpose into XST [c][tok] ----
    {
        const float4* xg = reinterpret_cast<const float4*>(x + (size_t)b * NTOK * DIM);
        #pragma unroll
        for (int u = 0; u < 6; ++u) {
            int e = tid + u * 256;               // 1536 float4 total
            float4 v = xg[e];
            int tok = e / 24, c = (e % 24) * 4;
            sm[XST + (c + 0) * 66 + tok] = v.x;
            sm[XST + (c + 1) * 66 + tok] = v.y;
            sm[XST + (c + 2) * 66 + tok] = v.z;
            sm[XST + (c + 3) * 66 + tok] = v.w;
        }
    }
    __syncthreads();

    const int wrp  = tid >> 5;   // warp id 0..7
    const int ln   = tid & 31;

    // =================== QKV GEMM (f32x2, token-row pairs) ===================
    // pass p: token pairs (2rp,2rp+1), rp = wrp + 8i (i<4); cols ln + 32j (j<3)
    #pragma unroll 1
    for (int p = 0; p < 3; ++p) {
        ull acc[4][3];
        #pragma unroll
        for (int j = 0; j < 3; ++j) {
            float bj = qkv_b[p * 96 + ln + 32 * j];
            ull pb = pk(bj, bj);
            #pragma unroll
            for (int i = 0; i < 4; ++i) acc[i][j] = pb;
        }

        #pragma unroll 1
        for (int kb = 0; kb < 96; kb += 16) {
            __syncthreads();
            for (int e = tid; e < 384; e += 256) {        // stage W chunk [16][96]
                int r = e / 24, c4 = e % 24;
                reinterpret_cast<float4*>(sm + WST)[e] =
                    *reinterpret_cast<const float4*>(
                        qkv_w + (size_t)(kb + r) * 288 + p * 96 + c4 * 4);
            }
            __syncthreads();

            #pragma unroll
            for (int kk = 0; kk < 16; ++kk) {
                ull xp[4];
                #pragma unroll
                for (int i = 0; i < 4; ++i)               // warp-broadcast LDS.64
                    xp[i] = *reinterpret_cast<const ull*>(
                        &sm[XST + (kb + kk) * 66 + 2 * (wrp + 8 * i)]);
                #pragma unroll
                for (int j = 0; j < 3; ++j) {
                    float wv = sm[WST + kk * 96 + ln + 32 * j];
                    ull wp = pk(wv, wv);
                    #pragma unroll
                    for (int i = 0; i < 4; ++i)
                        acc[i][j] = f2fma(xp[i], wp, acc[i][j]);
                }
            }
        }

        const int base   = (p == 0) ? QT : (p == 1) ? KT : VT;
        const int stride = (p == 1) ? 68 : 66;
        const ull qscale = pk(0.25f, 0.25f);              // hd^-0.5 = 16^-0.5
        #pragma unroll
        for (int j = 0; j < 3; ++j) {
            int c = ln + 32 * j;
            #pragma unroll
            for (int i = 0; i < 4; ++i) {
                ull v = (p == 0) ? f2mul(acc[i][j], qscale) : acc[i][j];
                *reinterpret_cast<ull*>(&sm[base + c * stride + 2 * (wrp + 8 * i)]) = v;
            }
        }
    }
    __syncthreads();

    // =========================== attention ===========================
    const float* cw   = cmb + (size_t)(b & (NW - 1)) * (HEADS * 4096);
    const int ty16 = tid >> 4;      // row group: rows 4*ty16 .. 4*ty16+3
    const int tx16 = tid & 15;      // col group (QK) / channel (PV)
    const int m0   = tx16 * 4;

    #pragma unroll 1
    for (int h = 0; h < HEADS; ++h) {
        const int cb = h * 16;

        // ---- QK^T: q token-pairs (f32x2) x 4 key columns ----
        ull a2[2][4] = {{0ull,0ull,0ull,0ull},{0ull,0ull,0ull,0ull}};
        #pragma unroll
        for (int d = 0; d < 16; ++d) {
            const float* qrow = &sm[QT + (cb + d) * 66 + 4 * ty16];
            ull qp0 = *reinterpret_cast<const ull*>(qrow);      // rows 4t,4t+1
            ull qp1 = *reinterpret_cast<const ull*>(qrow + 2);  // rows 4t+2,4t+3
            float4 kv = *reinterpret_cast<const float4*>(&sm[KT + (cb + d) * 68 + m0]);
            ull kp;
            kp = pk(kv.x, kv.x); a2[0][0]=f2fma(qp0,kp,a2[0][0]); a2[1][0]=f2fma(qp1,kp,a2[1][0]);
            kp = pk(kv.y, kv.y); a2[0][1]=f2fma(qp0,kp,a2[0][1]); a2[1][1]=f2fma(qp1,kp,a2[1][1]);
            kp = pk(kv.z, kv.z); a2[0][2]=f2fma(qp0,kp,a2[0][2]); a2[1][2]=f2fma(qp1,kp,a2[1][2]);
            kp = pk(kv.w, kv.w); a2[0][3]=f2fma(qp0,kp,a2[0][3]); a2[1][3]=f2fma(qp1,kp,a2[1][3]);
        }
        #pragma unroll
        for (int rr = 0; rr < 4; ++rr) {
            int r = ty16 * 4 + rr;
            float4 cv = *reinterpret_cast<const float4*>(&cw[h * 4096 + r * 64 + m0]);
            float lo, hi, l0, l1, l2, l3;
            upk(a2[rr >> 1][0], lo, hi); l0 = (rr & 1) ? hi : lo;
            upk(a2[rr >> 1][1], lo, hi); l1 = (rr & 1) ? hi : lo;
            upk(a2[rr >> 1][2], lo, hi); l2 = (rr & 1) ? hi : lo;
            upk(a2[rr >> 1][3], lo, hi); l3 = (rr & 1) ? hi : lo;
            *reinterpret_cast<float4*>(&sm[ATTN + r * 68 + m0]) =
                make_float4(l0 + cv.x, l1 + cv.y, l2 + cv.z, l3 + cv.w);
        }
        __syncthreads();

        // ---- softmax: 4 threads/row, 16 cols each, shfl width 4 ----
        {
            int row = tid >> 2;
            int c0  = (tid & 3) * 16;
            float* rp = sm + ATTN + row * 68 + c0;
            float4 v0 = *reinterpret_cast<float4*>(rp);
            float4 v1 = *reinterpret_cast<float4*>(rp + 4);
            float4 v2 = *reinterpret_cast<float4*>(rp + 8);
            float4 v3 = *reinterpret_cast<float4*>(rp + 12);
            float mx = fmaxf(fmaxf(fmaxf(v0.x,v0.y),fmaxf(v0.z,v0.w)),
                       fmaxf(fmaxf(fmaxf(v1.x,v1.y),fmaxf(v1.z,v1.w)),
                       fmaxf(fmaxf(fmaxf(v2.x,v2.y),fmaxf(v2.z,v2.w)),
                             fmaxf(fmaxf(v3.x,v3.y),fmaxf(v3.z,v3.w)))));
            mx = fmaxf(mx, __shfl_xor_sync(0xffffffffu, mx, 1, 4));
            mx = fmaxf(mx, __shfl_xor_sync(0xffffffffu, mx, 2, 4));
            v0.x=__expf(v0.x-mx); v0.y=__expf(v0.y-mx); v0.z=__expf(v0.z-mx); v0.w=__expf(v0.w-mx);
            v1.x=__expf(v1.x-mx); v1.y=__expf(v1.y-mx); v1.z=__expf(v1.z-mx); v1.w=__expf(v1.w-mx);
            v2.x=__expf(v2.x-mx); v2.y=__expf(v2.y-mx); v2.z=__expf(v2.z-mx); v2.w=__expf(v2.w-mx);
            v3.x=__expf(v3.x-mx); v3.y=__expf(v3.y-mx); v3.z=__expf(v3.z-mx); v3.w=__expf(v3.w-mx);
            float s = (v0.x+v0.y+v0.z+v0.w) + (v1.x+v1.y+v1.z+v1.w)
                    + (v2.x+v2.y+v2.z+v2.w) + (v3.x+v3.y+v3.z+v3.w);
            s += __shfl_xor_sync(0xffffffffu, s, 1, 4);
            s += __shfl_xor_sync(0xffffffffu, s, 2, 4);
            float inv = 1.0f / s;
            v0.x*=inv; v0.y*=inv; v0.z*=inv; v0.w*=inv;
            v1.x*=inv; v1.y*=inv; v1.z*=inv; v1.w*=inv;
            v2.x*=inv; v2.y*=inv; v2.z*=inv; v2.w*=inv;
            v3.x*=inv; v3.y*=inv; v3.z*=inv; v3.w*=inv;
            *reinterpret_cast<float4*>(rp)      = v0;
            *reinterpret_cast<float4*>(rp + 4)  = v1;
            *reinterpret_cast<float4*>(rp + 8)  = v2;
            *reinterpret_cast<float4*>(rp + 12) = v3;
        }
        __syncthreads();

        // ---- PV: f32x2 pairs over contraction m; out channel c = cb+tx16 ----
        {
            const int c = cb + tx16;
            ull acc2[4] = {0ull, 0ull, 0ull, 0ull};
            #pragma unroll 8
            for (int m2 = 0; m2 < 32; ++m2) {
                ull vv = *reinterpret_cast<const ull*>(&sm[VT + c * 66 + 2 * m2]);
                #pragma unroll
                for (int i = 0; i < 4; ++i) {
                    ull pp = *reinterpret_cast<const ull*>(
                        &sm[ATTN + (ty16 * 4 + i) * 68 + 2 * m2]);
                    acc2[i] = f2fma(pp, vv, acc2[i]);
                }
            }
            // o^T overwrites this head's (now dead) Q columns in QT
            #pragma unroll
            for (int i = 0; i < 4; ++i) {
                float lo, hi; upk(acc2[i], lo, hi);
                sm[QT + c * 66 + ty16 * 4 + i] = lo + hi;
            }
        }
        __syncthreads();
    }

    // =================== proj GEMM (input o^T already in QT) ===================
    {
        ull acc[4][3];
        #pragma unroll
        for (int j = 0; j < 3; ++j) {
            float bj = proj_b[ln + 32 * j];
            ull pb = pk(bj, bj);
            #pragma unroll
            for (int i = 0; i < 4; ++i) acc[i][j] = pb;
        }

        #pragma unroll 1
        for (int kb = 0; kb < 96; kb += 16) {
            __syncthreads();
            for (int e = tid; e < 384; e += 256) {
                int r = e / 24, c4 = e % 24;
                reinterpret_cast<float4*>(sm + WST)[e] =
                    *reinterpret_cast<const float4*>(
                        proj_w + (size_t)(kb + r) * 96 + c4 * 4);
            }
            __syncthreads();

            #pragma unroll
            for (int kk = 0; kk < 16; ++kk) {
                ull xp[4];
                #pragma unroll
                for (int i = 0; i < 4; ++i)
                    xp[i] = *reinterpret_cast<const ull*>(
                        &sm[QT + (kb + kk) * 66 + 2 * (wrp + 8 * i)]);
                #pragma unroll
                for (int j = 0; j < 3; ++j) {
                    float wv = sm[WST + kk * 96 + ln + 32 * j];
                    ull wp = pk(wv, wv);
                    #pragma unroll
                    for (int i = 0; i < 4; ++i)
                        acc[i][j] = f2fma(xp[i], wp, acc[i][j]);
                }
            }
        }

        float* og = out + (size_t)b * NTOK * DIM;
        #pragma unroll
        for (int i = 0; i < 4; ++i) {
            int r0 = 2 * (wrp + 8 * i);
            #pragma unroll
            for (int j = 0; j < 3; ++j) {
                int c = ln + 32 * j;
                float lo, hi; upk(acc[i][j], lo, hi);
                og[(size_t)r0 * 96 + c]       = lo;
                og[(size_t)(r0 + 1) * 96 + c] = hi;
            }
        }
    }
}

extern "C" void kernel_launch(void* const* d_in, const int* in_sizes, int n_in,
                              void* d_out, int out_size)
{
    const float* x      = (const float*)d_in[0];
    const float* mask   = (const float*)d_in[1];
    const float* qkv_w  = (const float*)d_in[2];
    const float* qkv_b  = (const float*)d_in[3];
    const float* proj_w = (const float*)d_in[4];
    const float* proj_b = (const float*)d_in[5];
    const float* rpb    = (const float*)d_in[6];
    const int*   ridx   = (const int*)d_in[7];
    float* out = (float*)d_out;

    const int n_windows = in_sizes[0] / (NTOK * DIM);   // 8192

    cudaFuncSetAttribute(win_attn_kernel,
                         cudaFuncAttributeMaxDynamicSharedMemorySize,
                         SMEM_FLOATS * sizeof(float));

    // 1) fold rpb-gather + shift-mask into one combined table
    const int total = NW * HEADS * NTOK * NTOK;
    prep_kernel<<<(total + 255) / 256, 256>>>(rpb, ridx, mask);
    // 2) fused window attention, one CTA per window
    win_attn_kernel<<<n_windows, 256, SMEM_FLOATS * sizeof(float)>>>(
        x, qkv_w, qkv_b, proj_w, proj_b, out);
}